// round 1
// baseline (speedup 1.0000x reference)
#include <cuda_runtime.h>

#define BATCH  4
#define SEQ    2048
#define DM     768
#define NHEADS 12
#define HD     64
#define TOK    (BATCH * SEQ)     // 8192
#define QKVC   (3 * DM)          // 2304

// Scratch (device globals: allocation-free per harness rules)
__device__ float g_wqkv[(size_t)DM * QKVC];      // packed [e][3*768] weight
__device__ float g_bqkv[QKVC];                   // packed qkv bias
__device__ float g_qkv[(size_t)TOK * QKVC];      // q|k|v per token
__device__ float g_z[(size_t)TOK * DM];          // attention output (pre-proj)

// ---------------------------------------------------------------------------
// Pack W_Q/W_K/W_V [N, DM, HD] into row-major [DM, 3*DM] so QKV is one GEMM.
// ---------------------------------------------------------------------------
__global__ void pack_w_kernel(const float* __restrict__ WQ,
                              const float* __restrict__ WK,
                              const float* __restrict__ WV,
                              const float* __restrict__ bQ,
                              const float* __restrict__ bK,
                              const float* __restrict__ bV) {
    int idx = blockIdx.x * blockDim.x + threadIdx.x;
    if (idx < DM * QKVC) {
        int e = idx / QKVC;
        int c = idx - e * QKVC;
        int p = c / DM;
        int nh = c - p * DM;
        const float* W = (p == 0) ? WQ : (p == 1) ? WK : WV;
        int n = nh / HD;
        int h = nh - n * HD;
        g_wqkv[idx] = W[((size_t)n * DM + e) * HD + h];
    }
    if (idx < QKVC) {
        int p = idx / DM;
        int nh = idx - p * DM;
        const float* bb = (p == 0) ? bQ : (p == 1) ? bK : bV;
        g_bqkv[idx] = bb[nh];
    }
}

// ---------------------------------------------------------------------------
// SGEMM: C[M,N] = A[M,K] @ B[K,N] + bias[N]   (all row-major)
// 128x64 tile, BK=16, 256 threads, 8x4 per-thread microtile.
// M%128==0, N%64==0, K%16==0 hold for all uses here.
// ---------------------------------------------------------------------------
#define GBM 128
#define GBN 64
#define GBK 16

__global__ __launch_bounds__(256)
void sgemm_bias_kernel(const float* __restrict__ A, const float* __restrict__ B,
                       const float* __restrict__ bias, float* __restrict__ C,
                       int M, int N, int K) {
    __shared__ float As[GBM][GBK + 1];
    __shared__ float Bs[GBK][GBN];
    int tid = threadIdx.x;
    int tx = tid & 15;        // 16 col-groups of 4
    int ty = tid >> 4;        // 16 row-groups of 8
    int m0 = blockIdx.y * GBM;
    int n0 = blockIdx.x * GBN;

    float acc[8][4];
#pragma unroll
    for (int i = 0; i < 8; i++)
#pragma unroll
        for (int j = 0; j < 4; j++) acc[i][j] = 0.f;

    for (int k0 = 0; k0 < K; k0 += GBK) {
        // A tile: 128x16 = 512 float4, 2 per thread
#pragma unroll
        for (int it = 0; it < 2; it++) {
            int f = tid + it * 256;
            int row = f >> 2, quad = f & 3;
            float4 a4 = *(const float4*)(A + (size_t)(m0 + row) * K + k0 + quad * 4);
            As[row][quad * 4 + 0] = a4.x;
            As[row][quad * 4 + 1] = a4.y;
            As[row][quad * 4 + 2] = a4.z;
            As[row][quad * 4 + 3] = a4.w;
        }
        // B tile: 16x64 = 256 float4, 1 per thread
        {
            int row = tid >> 4, quad = tid & 15;
            float4 b4 = *(const float4*)(B + (size_t)(k0 + row) * N + n0 + quad * 4);
            *(float4*)&Bs[row][quad * 4] = b4;
        }
        __syncthreads();
#pragma unroll
        for (int kk = 0; kk < GBK; kk++) {
            float a[8];
#pragma unroll
            for (int i = 0; i < 8; i++) a[i] = As[ty * 8 + i][kk];
            float4 b4 = *(float4*)&Bs[kk][tx * 4];
#pragma unroll
            for (int i = 0; i < 8; i++) {
                acc[i][0] += a[i] * b4.x;
                acc[i][1] += a[i] * b4.y;
                acc[i][2] += a[i] * b4.z;
                acc[i][3] += a[i] * b4.w;
            }
        }
        __syncthreads();
    }

    float4 bv = *(const float4*)(bias + n0 + tx * 4);
#pragma unroll
    for (int i = 0; i < 8; i++) {
        float4 o;
        o.x = acc[i][0] + bv.x;
        o.y = acc[i][1] + bv.y;
        o.z = acc[i][2] + bv.z;
        o.w = acc[i][3] + bv.w;
        *(float4*)(C + (size_t)(m0 + ty * 8 + i) * N + n0 + tx * 4) = o;
    }
}

// ---------------------------------------------------------------------------
// Causal flash attention (fp32, online softmax).
// Grid: (S/64, NHEADS, BATCH). Block 256 (16x16 thread grid).
// Q-tile 64 rows, K/V tile 32 rows. Per thread: 4 q-rows, score cols
// {tx, tx+16}, output cols tx*4..+3. Scores reduced across 16-lane groups.
// ---------------------------------------------------------------------------
__global__ __launch_bounds__(256)
void attn_kernel() {
    int qt = blockIdx.x, n = blockIdx.y, b = blockIdx.z;
    int q0 = qt * 64;

    __shared__ float Qs[64][64];     // [r][d]            16.0 KB
    __shared__ float Kst[64][33];    // [d][c] transposed  8.25 KB
    __shared__ float Vs[32][64];     // [c][h]             8.0 KB
    __shared__ float Ps[64][33];     // [r][c]             8.25 KB

    int tid = threadIdx.x;
    int tx = tid & 15;
    int ty = tid >> 4;

    // Load Q tile (64x64), coalesced float4
#pragma unroll
    for (int it = 0; it < 4; it++) {
        int f = tid + it * 256;
        int r = f >> 4, quad = f & 15;
        float4 q4 = *(const float4*)(g_qkv + (size_t)(b * SEQ + q0 + r) * QKVC
                                     + n * HD + quad * 4);
        *(float4*)&Qs[r][quad * 4] = q4;
    }

    float m[4], l[4], acc[4][4];
#pragma unroll
    for (int i = 0; i < 4; i++) {
        m[i] = -1e30f;
        l[i] = 0.f;
#pragma unroll
        for (int j = 0; j < 4; j++) acc[i][j] = 0.f;
    }

    const float scale = 0.125f;  // 1/sqrt(64)

    for (int k0 = 0; k0 <= q0 + 32; k0 += 32) {
        __syncthreads();  // prior iter's Ps/Vs reads done before overwrite
        // Load K (transposed into [d][c]) and V tiles
#pragma unroll
        for (int it = 0; it < 2; it++) {
            int f = tid + it * 256;
            int c = f >> 4, quad = f & 15;
            size_t base = (size_t)(b * SEQ + k0 + c) * QKVC + n * HD + quad * 4;
            float4 k4 = *(const float4*)(g_qkv + DM + base);
            Kst[quad * 4 + 0][c] = k4.x;
            Kst[quad * 4 + 1][c] = k4.y;
            Kst[quad * 4 + 2][c] = k4.z;
            Kst[quad * 4 + 3][c] = k4.w;
            float4 v4 = *(const float4*)(g_qkv + 2 * DM + base);
            *(float4*)&Vs[c][quad * 4] = v4;
        }
        __syncthreads();

        // Scores: s[i][jj] for rows ty*4+i, cols tx + 16*jj
        float s[4][2];
#pragma unroll
        for (int i = 0; i < 4; i++) { s[i][0] = 0.f; s[i][1] = 0.f; }
#pragma unroll 8
        for (int d = 0; d < 64; d++) {
            float kv0 = Kst[d][tx];
            float kv1 = Kst[d][tx + 16];
#pragma unroll
            for (int i = 0; i < 4; i++) {
                float qv = Qs[ty * 4 + i][d];
                s[i][0] += qv * kv0;
                s[i][1] += qv * kv1;
            }
        }

        bool need_mask = (k0 + 31 > q0);
#pragma unroll
        for (int i = 0; i < 4; i++) {
            int qg = q0 + ty * 4 + i;
#pragma unroll
            for (int jj = 0; jj < 2; jj++) {
                int kg = k0 + tx + 16 * jj;
                float v = s[i][jj] * scale;
                if (need_mask && kg > qg) v = -1e30f;
                s[i][jj] = v;
            }
        }

        // Online softmax update + write P
#pragma unroll
        for (int i = 0; i < 4; i++) {
            float rmax = fmaxf(s[i][0], s[i][1]);
#pragma unroll
            for (int off = 1; off < 16; off <<= 1)
                rmax = fmaxf(rmax, __shfl_xor_sync(0xffffffffu, rmax, off));
            float newm = fmaxf(m[i], rmax);
            float p0 = __expf(s[i][0] - newm);
            float p1 = __expf(s[i][1] - newm);
            float rsum = p0 + p1;
#pragma unroll
            for (int off = 1; off < 16; off <<= 1)
                rsum += __shfl_xor_sync(0xffffffffu, rsum, off);
            float alpha = __expf(m[i] - newm);
            l[i] = l[i] * alpha + rsum;
            m[i] = newm;
#pragma unroll
            for (int j = 0; j < 4; j++) acc[i][j] *= alpha;
            Ps[ty * 4 + i][tx] = p0;
            Ps[ty * 4 + i][tx + 16] = p1;
        }
        __syncthreads();

        // O += P @ V  (acc cols tx*4..+3)
#pragma unroll 4
        for (int c = 0; c < 32; c++) {
            float4 v4 = *(float4*)&Vs[c][tx * 4];
#pragma unroll
            for (int i = 0; i < 4; i++) {
                float p = Ps[ty * 4 + i][c];
                acc[i][0] += p * v4.x;
                acc[i][1] += p * v4.y;
                acc[i][2] += p * v4.z;
                acc[i][3] += p * v4.w;
            }
        }
    }

    // Epilogue: normalize and write z
#pragma unroll
    for (int i = 0; i < 4; i++) {
        float inv = 1.f / l[i];
        float4 o;
        o.x = acc[i][0] * inv;
        o.y = acc[i][1] * inv;
        o.z = acc[i][2] * inv;
        o.w = acc[i][3] * inv;
        *(float4*)(g_z + (size_t)(b * SEQ + q0 + ty * 4 + i) * DM
                   + n * HD + tx * 4) = o;
    }
}

// ---------------------------------------------------------------------------
extern "C" void kernel_launch(void* const* d_in, const int* in_sizes, int n_in,
                              void* d_out, int out_size) {
    const float* x  = (const float*)d_in[0];
    const float* WQ = (const float*)d_in[1];
    const float* WK = (const float*)d_in[2];
    const float* WV = (const float*)d_in[3];
    const float* WO = (const float*)d_in[4];
    const float* bQ = (const float*)d_in[5];
    const float* bK = (const float*)d_in[6];
    const float* bV = (const float*)d_in[7];
    const float* bO = (const float*)d_in[8];
    float* out = (float*)d_out;

    float *wqkv, *bqkv, *qkv, *z;
    cudaGetSymbolAddress((void**)&wqkv, g_wqkv);
    cudaGetSymbolAddress((void**)&bqkv, g_bqkv);
    cudaGetSymbolAddress((void**)&qkv,  g_qkv);
    cudaGetSymbolAddress((void**)&z,    g_z);

    // 1) pack weights + biases
    pack_w_kernel<<<(DM * QKVC + 255) / 256, 256>>>(WQ, WK, WV, bQ, bK, bV);

    // 2) QKV projection: [8192,768] @ [768,2304] + b
    {
        dim3 grid(QKVC / GBN, TOK / GBM);
        sgemm_bias_kernel<<<grid, 256>>>(x, wqkv, bqkv, qkv, TOK, QKVC, DM);
    }

    // 3) causal flash attention -> z
    {
        dim3 grid(SEQ / 64, NHEADS, BATCH);
        attn_kernel<<<grid, 256>>>();
    }

    // 4) output projection: [8192,768] @ W_O[768,768] + b_O
    {
        dim3 grid(DM / GBN, TOK / GBM);
        sgemm_bias_kernel<<<grid, 256>>>(z, WO, bO, out, TOK, DM, DM);
    }
}

// round 4
// speedup vs baseline: 1.5153x; 1.5153x over previous
#include <cuda_runtime.h>
#include <cstdint>

#define BATCH  4
#define SEQ    2048
#define DM     768
#define NHEADS 12
#define HD     64
#define TOK    (BATCH * SEQ)     // 8192
#define QKVC   (3 * DM)          // 2304

// ---------------- scratch (device globals; allocation-free) ----------------
__device__ float g_wqkvT[(size_t)QKVC * DM];   // B^T (tf32-rounded): [2304][768]
__device__ float g_woT[(size_t)DM * DM];       // B^T (tf32-rounded): [768][768]
__device__ float g_bqkv[QKVC];
__device__ float g_qkv[(size_t)TOK * QKVC];    // q|k|v per token
__device__ float g_z[(size_t)TOK * DM];

// ---------------------------- PTX helpers ----------------------------------
__device__ __forceinline__ uint32_t smem_u32(const void* p) {
    uint32_t a;
    asm("{ .reg .u64 t; cvta.to.shared.u64 t, %1; cvt.u32.u64 %0, t; }"
        : "=r"(a) : "l"(p));
    return a;
}
__device__ __forceinline__ void cpa16(uint32_t s, const void* g) {
    asm volatile("cp.async.cg.shared.global [%0], [%1], 16;" :: "r"(s), "l"(g));
}
#define CP_COMMIT() asm volatile("cp.async.commit_group;" ::: "memory")
#define CP_WAIT(n)  asm volatile("cp.async.wait_group %0;" :: "n"(n) : "memory")

__device__ __forceinline__ uint32_t f2tf32(float f) {
    uint32_t r;
    asm("cvt.rna.tf32.f32 %0, %1;" : "=r"(r) : "f"(f));
    return r;
}
__device__ __forceinline__ void mma_tf32(float* d, const uint32_t* a,
                                         const uint32_t* b) {
    asm volatile(
        "mma.sync.aligned.m16n8k8.row.col.f32.tf32.tf32.f32 "
        "{%0,%1,%2,%3}, {%4,%5,%6,%7}, {%8,%9}, {%0,%1,%2,%3};"
        : "+f"(d[0]), "+f"(d[1]), "+f"(d[2]), "+f"(d[3])
        : "r"(a[0]), "r"(a[1]), "r"(a[2]), "r"(a[3]), "r"(b[0]), "r"(b[1]));
}

// ---------------------------------------------------------------------------
// Pack: transpose weights into K-major B^T (rounded to tf32) + pack qkv bias
// ---------------------------------------------------------------------------
__global__ void pack_w_kernel(const float* __restrict__ WQ,
                              const float* __restrict__ WK,
                              const float* __restrict__ WV,
                              const float* __restrict__ WO,
                              const float* __restrict__ bQ,
                              const float* __restrict__ bK,
                              const float* __restrict__ bV) {
    int idx = blockIdx.x * blockDim.x + threadIdx.x;
    if (idx < QKVC * DM) {
        int c = idx / DM;          // output column 0..2303
        int e = idx - c * DM;      // k index
        int p = c / DM;
        int nh = c - p * DM;
        const float* W = (p == 0) ? WQ : (p == 1) ? WK : WV;
        int n = nh / HD;
        int h = nh - n * HD;
        g_wqkvT[idx] = __uint_as_float(f2tf32(W[((size_t)n * DM + e) * HD + h]));
    }
    if (idx < DM * DM) {
        int e = idx / DM;          // output column (model dim)
        int nh = idx - e * DM;     // k index (n,h)
        g_woT[idx] = __uint_as_float(f2tf32(WO[(size_t)nh * DM + e]));
    }
    if (idx < QKVC) {
        int p = idx / DM;
        int nh = idx - p * DM;
        const float* bb = (p == 0) ? bQ : (p == 1) ? bK : bV;
        g_bqkv[idx] = bb[nh];
    }
}

// ---------------------------------------------------------------------------
// TF32 mma.sync GEMM:  C[M,N] = A[M,768] * Bt[N,768]^T + bias[N]
// Block 128x128, K-chunk 32, 8 warps (4x2), warp tile 32x64 (2x8 m16n8k8).
// cp.async double-buffered. Smem row stride 36 floats (conflict-free frags).
// ---------------------------------------------------------------------------
#define BM 128
#define BN 128
#define BK 32
#define STR 36                       // floats per smem row
#define NCHUNK (DM / BK)             // 24
#define BUF_FLOATS (2 * BM * STR)    // A tile + B tile = 9216 floats
#define GEMM_SMEM (2 * BUF_FLOATS * 4)   // 73728 bytes

__global__ __launch_bounds__(256)
void gemm_mma_kernel(const float* __restrict__ A, const float* __restrict__ Bt,
                     const float* __restrict__ bias, float* __restrict__ C,
                     int N) {
    extern __shared__ float smem[];
    uint32_t sb = smem_u32(smem);
    int tid = threadIdx.x;
    int lane = tid & 31;
    int wid = tid >> 5;
    int warpM = wid & 3;          // 4 along M
    int warpN = wid >> 2;         // 2 along N
    int m0 = blockIdx.y * BM;
    int n0 = blockIdx.x * BN;

    // ---- chunk loader: A[128][32] + B[128][32] as 16B cp.async ----
    auto load_chunk = [&](int c, int buf) {
        uint32_t abase = sb + buf * (BUF_FLOATS * 4);
        uint32_t bbase = abase + BM * STR * 4;
        int k0 = c * BK;
        const float* ap = A + (size_t)m0 * DM + k0;
        const float* bp = Bt + (size_t)n0 * DM + k0;
#pragma unroll
        for (int it = 0; it < 4; it++) {
            int t = tid + it * 256;
            int row = t >> 3, seg = t & 7;
            cpa16(abase + row * (STR * 4) + seg * 16,
                  ap + (size_t)row * DM + seg * 4);
        }
#pragma unroll
        for (int it = 0; it < 4; it++) {
            int t = tid + it * 256;
            int row = t >> 3, seg = t & 7;
            cpa16(bbase + row * (STR * 4) + seg * 16,
                  bp + (size_t)row * DM + seg * 4);
        }
        CP_COMMIT();
    };

    float acc[2][8][4];
#pragma unroll
    for (int mi = 0; mi < 2; mi++)
#pragma unroll
        for (int ni = 0; ni < 8; ni++)
#pragma unroll
            for (int j = 0; j < 4; j++) acc[mi][ni][j] = 0.f;

    load_chunk(0, 0);
    load_chunk(1, 1);
    CP_WAIT(1);
    __syncthreads();

    for (int c = 0; c < NCHUNK; c++) {
        int buf = c & 1;
        const float* As = smem + buf * BUF_FLOATS;
        const float* Bs = As + BM * STR;
        int r0 = warpM * 32 + (lane >> 2);
        int nr0 = warpN * 64 + (lane >> 2);
#pragma unroll
        for (int ks = 0; ks < 4; ks++) {
            int kc = ks * 8 + (lane & 3);
            uint32_t a[2][4], b[8][2];
#pragma unroll
            for (int mi = 0; mi < 2; mi++) {
                a[mi][0] = f2tf32(As[(r0 + mi * 16) * STR + kc]);
                a[mi][1] = f2tf32(As[(r0 + mi * 16 + 8) * STR + kc]);
                a[mi][2] = f2tf32(As[(r0 + mi * 16) * STR + kc + 4]);
                a[mi][3] = f2tf32(As[(r0 + mi * 16 + 8) * STR + kc + 4]);
            }
#pragma unroll
            for (int ni = 0; ni < 8; ni++) {
                // weights pre-rounded to tf32 in pack kernel
                b[ni][0] = __float_as_uint(Bs[(nr0 + ni * 8) * STR + kc]);
                b[ni][1] = __float_as_uint(Bs[(nr0 + ni * 8) * STR + kc + 4]);
            }
#pragma unroll
            for (int mi = 0; mi < 2; mi++)
#pragma unroll
                for (int ni = 0; ni < 8; ni++)
                    mma_tf32(acc[mi][ni], a[mi], b[ni]);
        }
        __syncthreads();                 // done reading buf
        if (c + 2 < NCHUNK) {
            load_chunk(c + 2, buf);
            CP_WAIT(1);
        } else {
            CP_WAIT(0);
        }
        __syncthreads();                 // chunk c+1 visible to all
    }

    // ---- epilogue: direct STG.64 with bias ----
#pragma unroll
    for (int mi = 0; mi < 2; mi++)
#pragma unroll
        for (int h = 0; h < 2; h++) {
            int row = m0 + warpM * 32 + mi * 16 + (lane >> 2) + h * 8;
#pragma unroll
            for (int ni = 0; ni < 8; ni++) {
                int col = n0 + warpN * 64 + ni * 8 + (lane & 3) * 2;
                float2 bv = *(const float2*)(bias + col);
                float2 o;
                o.x = acc[mi][ni][h * 2 + 0] + bv.x;
                o.y = acc[mi][ni][h * 2 + 1] + bv.y;
                *(float2*)(C + (size_t)row * N + col) = o;
            }
        }
}

// ---------------------------------------------------------------------------
// Causal flash attention (fp32, online softmax) — unchanged (known-good)
// ---------------------------------------------------------------------------
__global__ __launch_bounds__(256)
void attn_kernel() {
    int qt = blockIdx.x, n = blockIdx.y, b = blockIdx.z;
    int q0 = qt * 64;

    __shared__ float Qs[64][64];
    __shared__ float Kst[64][33];
    __shared__ float Vs[32][64];
    __shared__ float Ps[64][33];

    int tid = threadIdx.x;
    int tx = tid & 15;
    int ty = tid >> 4;

#pragma unroll
    for (int it = 0; it < 4; it++) {
        int f = tid + it * 256;
        int r = f >> 4, quad = f & 15;
        float4 q4 = *(const float4*)(g_qkv + (size_t)(b * SEQ + q0 + r) * QKVC
                                     + n * HD + quad * 4);
        *(float4*)&Qs[r][quad * 4] = q4;
    }

    float m[4], l[4], acc[4][4];
#pragma unroll
    for (int i = 0; i < 4; i++) {
        m[i] = -1e30f;
        l[i] = 0.f;
#pragma unroll
        for (int j = 0; j < 4; j++) acc[i][j] = 0.f;
    }

    const float scale = 0.125f;

    for (int k0 = 0; k0 <= q0 + 32; k0 += 32) {
        __syncthreads();
#pragma unroll
        for (int it = 0; it < 2; it++) {
            int f = tid + it * 256;
            int c = f >> 4, quad = f & 15;
            size_t base = (size_t)(b * SEQ + k0 + c) * QKVC + n * HD + quad * 4;
            float4 k4 = *(const float4*)(g_qkv + DM + base);
            Kst[quad * 4 + 0][c] = k4.x;
            Kst[quad * 4 + 1][c] = k4.y;
            Kst[quad * 4 + 2][c] = k4.z;
            Kst[quad * 4 + 3][c] = k4.w;
            float4 v4 = *(const float4*)(g_qkv + 2 * DM + base);
            *(float4*)&Vs[c][quad * 4] = v4;
        }
        __syncthreads();

        float s[4][2];
#pragma unroll
        for (int i = 0; i < 4; i++) { s[i][0] = 0.f; s[i][1] = 0.f; }
#pragma unroll 8
        for (int d = 0; d < 64; d++) {
            float kv0 = Kst[d][tx];
            float kv1 = Kst[d][tx + 16];
#pragma unroll
            for (int i = 0; i < 4; i++) {
                float qv = Qs[ty * 4 + i][d];
                s[i][0] += qv * kv0;
                s[i][1] += qv * kv1;
            }
        }

        bool need_mask = (k0 + 31 > q0);
#pragma unroll
        for (int i = 0; i < 4; i++) {
            int qg = q0 + ty * 4 + i;
#pragma unroll
            for (int jj = 0; jj < 2; jj++) {
                int kg = k0 + tx + 16 * jj;
                float v = s[i][jj] * scale;
                if (need_mask && kg > qg) v = -1e30f;
                s[i][jj] = v;
            }
        }

#pragma unroll
        for (int i = 0; i < 4; i++) {
            float rmax = fmaxf(s[i][0], s[i][1]);
#pragma unroll
            for (int off = 1; off < 16; off <<= 1)
                rmax = fmaxf(rmax, __shfl_xor_sync(0xffffffffu, rmax, off));
            float newm = fmaxf(m[i], rmax);
            float p0 = __expf(s[i][0] - newm);
            float p1 = __expf(s[i][1] - newm);
            float rsum = p0 + p1;
#pragma unroll
            for (int off = 1; off < 16; off <<= 1)
                rsum += __shfl_xor_sync(0xffffffffu, rsum, off);
            float alpha = __expf(m[i] - newm);
            l[i] = l[i] * alpha + rsum;
            m[i] = newm;
#pragma unroll
            for (int j = 0; j < 4; j++) acc[i][j] *= alpha;
            Ps[ty * 4 + i][tx] = p0;
            Ps[ty * 4 + i][tx + 16] = p1;
        }
        __syncthreads();

#pragma unroll 4
        for (int c = 0; c < 32; c++) {
            float4 v4 = *(float4*)&Vs[c][tx * 4];
#pragma unroll
            for (int i = 0; i < 4; i++) {
                float p = Ps[ty * 4 + i][c];
                acc[i][0] += p * v4.x;
                acc[i][1] += p * v4.y;
                acc[i][2] += p * v4.z;
                acc[i][3] += p * v4.w;
            }
        }
    }

#pragma unroll
    for (int i = 0; i < 4; i++) {
        float inv = 1.f / l[i];
        float4 o;
        o.x = acc[i][0] * inv;
        o.y = acc[i][1] * inv;
        o.z = acc[i][2] * inv;
        o.w = acc[i][3] * inv;
        *(float4*)(g_z + (size_t)(b * SEQ + q0 + ty * 4 + i) * DM
                   + n * HD + tx * 4) = o;
    }
}

// ---------------------------------------------------------------------------
extern "C" void kernel_launch(void* const* d_in, const int* in_sizes, int n_in,
                              void* d_out, int out_size) {
    const float* x  = (const float*)d_in[0];
    const float* WQ = (const float*)d_in[1];
    const float* WK = (const float*)d_in[2];
    const float* WV = (const float*)d_in[3];
    const float* WO = (const float*)d_in[4];
    const float* bQ = (const float*)d_in[5];
    const float* bK = (const float*)d_in[6];
    const float* bV = (const float*)d_in[7];
    const float* bO = (const float*)d_in[8];
    float* out = (float*)d_out;

    float *wqkvT, *woT, *bqkv, *qkv, *z;
    cudaGetSymbolAddress((void**)&wqkvT, g_wqkvT);
    cudaGetSymbolAddress((void**)&woT,   g_woT);
    cudaGetSymbolAddress((void**)&bqkv,  g_bqkv);
    cudaGetSymbolAddress((void**)&qkv,   g_qkv);
    cudaGetSymbolAddress((void**)&z,     g_z);

    cudaFuncSetAttribute(gemm_mma_kernel,
                         cudaFuncAttributeMaxDynamicSharedMemorySize, GEMM_SMEM);

    // 1) pack weights (transposed, tf32-rounded) + bias
    pack_w_kernel<<<(QKVC * DM + 255) / 256, 256>>>(WQ, WK, WV, WO, bQ, bK, bV);

    // 2) QKV projection (tf32 mma.sync): [8192,768] x [2304,768]^T
    {
        dim3 grid(QKVC / BN, TOK / BM);
        gemm_mma_kernel<<<grid, 256, GEMM_SMEM>>>(x, wqkvT, bqkv, qkv, QKVC);
    }

    // 3) causal flash attention -> z
    {
        dim3 grid(SEQ / 64, NHEADS, BATCH);
        attn_kernel<<<grid, 256>>>();
    }

    // 4) output projection (tf32 mma.sync): [8192,768] x [768,768]^T
    {
        dim3 grid(DM / BN, TOK / BM);
        gemm_mma_kernel<<<grid, 256, GEMM_SMEM>>>(z, woT, bO, out, DM);
    }
}

// round 5
// speedup vs baseline: 3.4095x; 2.2500x over previous
#include <cuda_runtime.h>
#include <cstdint>

#define BATCH  4
#define SEQ    2048
#define DM     768
#define NHEADS 12
#define HD     64
#define TOK    (BATCH * SEQ)     // 8192
#define QKVC   (3 * DM)          // 2304

// ---------------- scratch (device globals; allocation-free) ----------------
__device__ float g_wqkvT[(size_t)QKVC * DM];   // B^T (tf32-rounded): [2304][768]
__device__ float g_woT[(size_t)DM * DM];       // B^T (tf32-rounded): [768][768]
__device__ float g_bqkv[QKVC];
__device__ float g_qkv[(size_t)TOK * QKVC];    // q|k|v per token
__device__ float g_z[(size_t)TOK * DM];

// ---------------------------- PTX helpers ----------------------------------
__device__ __forceinline__ uint32_t smem_u32(const void* p) {
    uint32_t a;
    asm("{ .reg .u64 t; cvta.to.shared.u64 t, %1; cvt.u32.u64 %0, t; }"
        : "=r"(a) : "l"(p));
    return a;
}
__device__ __forceinline__ void cpa16(uint32_t s, const void* g) {
    asm volatile("cp.async.cg.shared.global [%0], [%1], 16;" :: "r"(s), "l"(g));
}
#define CP_COMMIT() asm volatile("cp.async.commit_group;" ::: "memory")
#define CP_WAIT(n)  asm volatile("cp.async.wait_group %0;" :: "n"(n) : "memory")

__device__ __forceinline__ uint32_t f2tf32(float f) {
    uint32_t r;
    asm("cvt.rna.tf32.f32 %0, %1;" : "=r"(r) : "f"(f));
    return r;
}
__device__ __forceinline__ void mma_tf32(float* d, const uint32_t* a,
                                         const uint32_t* b) {
    asm volatile(
        "mma.sync.aligned.m16n8k8.row.col.f32.tf32.tf32.f32 "
        "{%0,%1,%2,%3}, {%4,%5,%6,%7}, {%8,%9}, {%0,%1,%2,%3};"
        : "+f"(d[0]), "+f"(d[1]), "+f"(d[2]), "+f"(d[3])
        : "r"(a[0]), "r"(a[1]), "r"(a[2]), "r"(a[3]), "r"(b[0]), "r"(b[1]));
}

// ---------------------------------------------------------------------------
// Pack: transpose weights into K-major B^T (rounded to tf32) + pack qkv bias
// ---------------------------------------------------------------------------
__global__ void pack_w_kernel(const float* __restrict__ WQ,
                              const float* __restrict__ WK,
                              const float* __restrict__ WV,
                              const float* __restrict__ WO,
                              const float* __restrict__ bQ,
                              const float* __restrict__ bK,
                              const float* __restrict__ bV) {
    int idx = blockIdx.x * blockDim.x + threadIdx.x;
    if (idx < QKVC * DM) {
        int c = idx / DM;
        int e = idx - c * DM;
        int p = c / DM;
        int nh = c - p * DM;
        const float* W = (p == 0) ? WQ : (p == 1) ? WK : WV;
        int n = nh / HD;
        int h = nh - n * HD;
        g_wqkvT[idx] = __uint_as_float(f2tf32(W[((size_t)n * DM + e) * HD + h]));
    }
    if (idx < DM * DM) {
        int e = idx / DM;
        int nh = idx - e * DM;
        g_woT[idx] = __uint_as_float(f2tf32(WO[(size_t)nh * DM + e]));
    }
    if (idx < QKVC) {
        int p = idx / DM;
        int nh = idx - p * DM;
        const float* bb = (p == 0) ? bQ : (p == 1) ? bK : bV;
        g_bqkv[idx] = bb[nh];
    }
}

// ---------------------------------------------------------------------------
// TF32 mma.sync GEMM (unchanged from round 4; 78us QKV / ~30us out-proj)
// ---------------------------------------------------------------------------
#define BM 128
#define BN 128
#define BK 32
#define STR 36
#define NCHUNK (DM / BK)
#define BUF_FLOATS (2 * BM * STR)
#define GEMM_SMEM (2 * BUF_FLOATS * 4)

__global__ __launch_bounds__(256)
void gemm_mma_kernel(const float* __restrict__ A, const float* __restrict__ Bt,
                     const float* __restrict__ bias, float* __restrict__ C,
                     int N) {
    extern __shared__ float smem[];
    uint32_t sb = smem_u32(smem);
    int tid = threadIdx.x;
    int lane = tid & 31;
    int wid = tid >> 5;
    int warpM = wid & 3;
    int warpN = wid >> 2;
    int m0 = blockIdx.y * BM;
    int n0 = blockIdx.x * BN;

    auto load_chunk = [&](int c, int buf) {
        uint32_t abase = sb + buf * (BUF_FLOATS * 4);
        uint32_t bbase = abase + BM * STR * 4;
        int k0 = c * BK;
        const float* ap = A + (size_t)m0 * DM + k0;
        const float* bp = Bt + (size_t)n0 * DM + k0;
#pragma unroll
        for (int it = 0; it < 4; it++) {
            int t = tid + it * 256;
            int row = t >> 3, seg = t & 7;
            cpa16(abase + row * (STR * 4) + seg * 16,
                  ap + (size_t)row * DM + seg * 4);
        }
#pragma unroll
        for (int it = 0; it < 4; it++) {
            int t = tid + it * 256;
            int row = t >> 3, seg = t & 7;
            cpa16(bbase + row * (STR * 4) + seg * 16,
                  bp + (size_t)row * DM + seg * 4);
        }
        CP_COMMIT();
    };

    float acc[2][8][4];
#pragma unroll
    for (int mi = 0; mi < 2; mi++)
#pragma unroll
        for (int ni = 0; ni < 8; ni++)
#pragma unroll
            for (int j = 0; j < 4; j++) acc[mi][ni][j] = 0.f;

    load_chunk(0, 0);
    load_chunk(1, 1);
    CP_WAIT(1);
    __syncthreads();

    for (int c = 0; c < NCHUNK; c++) {
        int buf = c & 1;
        const float* As = smem + buf * BUF_FLOATS;
        const float* Bs = As + BM * STR;
        int r0 = warpM * 32 + (lane >> 2);
        int nr0 = warpN * 64 + (lane >> 2);
#pragma unroll
        for (int ks = 0; ks < 4; ks++) {
            int kc = ks * 8 + (lane & 3);
            uint32_t a[2][4], b[8][2];
#pragma unroll
            for (int mi = 0; mi < 2; mi++) {
                a[mi][0] = f2tf32(As[(r0 + mi * 16) * STR + kc]);
                a[mi][1] = f2tf32(As[(r0 + mi * 16 + 8) * STR + kc]);
                a[mi][2] = f2tf32(As[(r0 + mi * 16) * STR + kc + 4]);
                a[mi][3] = f2tf32(As[(r0 + mi * 16 + 8) * STR + kc + 4]);
            }
#pragma unroll
            for (int ni = 0; ni < 8; ni++) {
                b[ni][0] = __float_as_uint(Bs[(nr0 + ni * 8) * STR + kc]);
                b[ni][1] = __float_as_uint(Bs[(nr0 + ni * 8) * STR + kc + 4]);
            }
#pragma unroll
            for (int mi = 0; mi < 2; mi++)
#pragma unroll
                for (int ni = 0; ni < 8; ni++)
                    mma_tf32(acc[mi][ni], a[mi], b[ni]);
        }
        __syncthreads();
        if (c + 2 < NCHUNK) {
            load_chunk(c + 2, buf);
            CP_WAIT(1);
        } else {
            CP_WAIT(0);
        }
        __syncthreads();
    }

#pragma unroll
    for (int mi = 0; mi < 2; mi++)
#pragma unroll
        for (int h = 0; h < 2; h++) {
            int row = m0 + warpM * 32 + mi * 16 + (lane >> 2) + h * 8;
#pragma unroll
            for (int ni = 0; ni < 8; ni++) {
                int col = n0 + warpN * 64 + ni * 8 + (lane & 3) * 2;
                float2 bv = *(const float2*)(bias + col);
                float2 o;
                o.x = acc[mi][ni][h * 2 + 0] + bv.x;
                o.y = acc[mi][ni][h * 2 + 1] + bv.y;
                *(float2*)(C + (size_t)row * N + col) = o;
            }
        }
}

// ---------------------------------------------------------------------------
// Flash attention with tf32 mma.sync.
// Block: 128 q-rows x 1 head. 8 warps, each owns m16. K-tile 64 keys,
// cp.async double-buffered. K smem stride 68, V stride 72 (both conflict-free
// for their b-frag patterns). P transposed acc->A-frag via intra-quad shfl.
// ---------------------------------------------------------------------------
#define AQ 128
#define AK 64
#define KSTR 68
#define VSTR 72
#define ATT_BUF (AK * KSTR + AK * VSTR)         // floats per buffer = 8960
#define ATT_SMEM (2 * ATT_BUF * 4)              // 71680 bytes

__global__ __launch_bounds__(256, 2)
void attn_mma_kernel() {
    extern __shared__ float smem[];
    uint32_t sb = smem_u32(smem);
    int tid = threadIdx.x;
    int lane = tid & 31;
    int wid = tid >> 5;
    int qq = lane >> 2;        // row-in-8
    int jp = lane & 3;

    int qi = gridDim.x - 1 - blockIdx.x;   // heavy blocks first
    int head = blockIdx.y, b = blockIdx.z;
    int q0 = qi * AQ;
    int nkt = 2 * qi + 2;      // k-tiles of 64

    // ---- load Q fragments once (pre-rounded tf32), rows wid*16 + qq (+8) ----
    uint32_t qa[8][4];
    {
        const float* qp0 = g_qkv + (size_t)(b * SEQ + q0 + wid * 16 + qq) * QKVC
                           + head * HD;
        const float* qp8 = qp0 + (size_t)8 * QKVC;
#pragma unroll
        for (int ks = 0; ks < 8; ks++) {
            qa[ks][0] = f2tf32(qp0[ks * 8 + jp]);
            qa[ks][1] = f2tf32(qp8[ks * 8 + jp]);
            qa[ks][2] = f2tf32(qp0[ks * 8 + jp + 4]);
            qa[ks][3] = f2tf32(qp8[ks * 8 + jp + 4]);
        }
    }

    // ---- K/V tile loader ----
    auto load_kv = [&](int t, int buf) {
        int k0 = t * AK;
        uint32_t kb = sb + buf * (ATT_BUF * 4);
        uint32_t vb = kb + AK * KSTR * 4;
#pragma unroll
        for (int it = 0; it < 4; it++) {
            int s = tid + it * 256;
            int row = s >> 4, seg = s & 15;
            size_t src = (size_t)(b * SEQ + k0 + row) * QKVC + head * HD + seg * 4;
            cpa16(kb + row * (KSTR * 4) + seg * 16, g_qkv + DM + src);
        }
#pragma unroll
        for (int it = 0; it < 4; it++) {
            int s = tid + it * 256;
            int row = s >> 4, seg = s & 15;
            size_t src = (size_t)(b * SEQ + k0 + row) * QKVC + head * HD + seg * 4;
            cpa16(vb + row * (VSTR * 4) + seg * 16, g_qkv + 2 * DM + src);
        }
        CP_COMMIT();
    };

    float oacc[8][4];
#pragma unroll
    for (int dn = 0; dn < 8; dn++)
#pragma unroll
        for (int j = 0; j < 4; j++) oacc[dn][j] = 0.f;
    float m0 = -1e30f, m1 = -1e30f, l0 = 0.f, l1 = 0.f;

    load_kv(0, 0);
    load_kv(1, 1);
    CP_WAIT(1);
    __syncthreads();

    const float scale = 0.125f;
    int row0 = q0 + wid * 16 + qq;          // global q row (lower half)

    for (int t = 0; t < nkt; t++) {
        int buf = t & 1;
        int k0 = t * AK;
        const float* Ks = smem + buf * ATT_BUF;
        const float* Vs = Ks + AK * KSTR;

        // ---- S = Q @ K^T ----
        float facc[8][4];
#pragma unroll
        for (int nf = 0; nf < 8; nf++)
#pragma unroll
            for (int j = 0; j < 4; j++) facc[nf][j] = 0.f;
#pragma unroll
        for (int ks = 0; ks < 8; ks++) {
            int kc = ks * 8 + jp;
#pragma unroll
            for (int nf = 0; nf < 8; nf++) {
                uint32_t bfr[2];
                bfr[0] = __float_as_uint(Ks[(nf * 8 + qq) * KSTR + kc]);
                bfr[1] = __float_as_uint(Ks[(nf * 8 + qq) * KSTR + kc + 4]);
                mma_tf32(facc[nf], qa[ks], bfr);
            }
        }

        // ---- scale + causal mask ----
        bool diag = (t >= nkt - 2);
#pragma unroll
        for (int nf = 0; nf < 8; nf++) {
            int kg = k0 + nf * 8 + 2 * jp;
#pragma unroll
            for (int e = 0; e < 4; e++) {
                int col = kg + (e & 1);
                int row = row0 + ((e >= 2) ? 8 : 0);
                float v = facc[nf][e] * scale;
                if (diag && col > row) v = -1e30f;
                facc[nf][e] = v;
            }
        }

        // ---- online softmax ----
        float mx0 = -1e30f, mx1 = -1e30f;
#pragma unroll
        for (int nf = 0; nf < 8; nf++) {
            mx0 = fmaxf(mx0, fmaxf(facc[nf][0], facc[nf][1]));
            mx1 = fmaxf(mx1, fmaxf(facc[nf][2], facc[nf][3]));
        }
        mx0 = fmaxf(mx0, __shfl_xor_sync(0xffffffffu, mx0, 1));
        mx0 = fmaxf(mx0, __shfl_xor_sync(0xffffffffu, mx0, 2));
        mx1 = fmaxf(mx1, __shfl_xor_sync(0xffffffffu, mx1, 1));
        mx1 = fmaxf(mx1, __shfl_xor_sync(0xffffffffu, mx1, 2));
        float nm0 = fmaxf(m0, mx0), nm1 = fmaxf(m1, mx1);
        float al0 = __expf(m0 - nm0), al1 = __expf(m1 - nm1);
        m0 = nm0; m1 = nm1;
        float rs0 = 0.f, rs1 = 0.f;
#pragma unroll
        for (int nf = 0; nf < 8; nf++) {
            facc[nf][0] = __expf(facc[nf][0] - nm0);
            facc[nf][1] = __expf(facc[nf][1] - nm0);
            facc[nf][2] = __expf(facc[nf][2] - nm1);
            facc[nf][3] = __expf(facc[nf][3] - nm1);
            rs0 += facc[nf][0] + facc[nf][1];
            rs1 += facc[nf][2] + facc[nf][3];
        }
        rs0 += __shfl_xor_sync(0xffffffffu, rs0, 1);
        rs0 += __shfl_xor_sync(0xffffffffu, rs0, 2);
        rs1 += __shfl_xor_sync(0xffffffffu, rs1, 1);
        rs1 += __shfl_xor_sync(0xffffffffu, rs1, 2);
        l0 = l0 * al0 + rs0;
        l1 = l1 * al1 + rs1;
#pragma unroll
        for (int dn = 0; dn < 8; dn++) {
            oacc[dn][0] *= al0; oacc[dn][1] *= al0;
            oacc[dn][2] *= al1; oacc[dn][3] *= al1;
        }

        // ---- O += P @ V : transpose P acc->A-frag via shfl, then mma ----
        int srcA = (lane & 28) | (jp >> 1);
        bool odd = jp & 1;
#pragma unroll
        for (int kt8 = 0; kt8 < 8; kt8++) {
            uint32_t pc0 = f2tf32(facc[kt8][0]);
            uint32_t pc1 = f2tf32(facc[kt8][1]);
            uint32_t pc2 = f2tf32(facc[kt8][2]);
            uint32_t pc3 = f2tf32(facc[kt8][3]);
            uint32_t s0 = __shfl_sync(0xffffffffu, pc0, srcA);
            uint32_t s1 = __shfl_sync(0xffffffffu, pc1, srcA);
            uint32_t s2 = __shfl_sync(0xffffffffu, pc2, srcA);
            uint32_t s3 = __shfl_sync(0xffffffffu, pc3, srcA);
            uint32_t u0 = __shfl_sync(0xffffffffu, pc0, srcA + 2);
            uint32_t u1 = __shfl_sync(0xffffffffu, pc1, srcA + 2);
            uint32_t u2 = __shfl_sync(0xffffffffu, pc2, srcA + 2);
            uint32_t u3 = __shfl_sync(0xffffffffu, pc3, srcA + 2);
            uint32_t pa[4];
            pa[0] = odd ? s1 : s0;
            pa[1] = odd ? s3 : s2;
            pa[2] = odd ? u1 : u0;
            pa[3] = odd ? u3 : u2;
#pragma unroll
            for (int dn = 0; dn < 8; dn++) {
                uint32_t bfr[2];
                bfr[0] = __float_as_uint(Vs[(kt8 * 8 + jp) * VSTR + dn * 8 + qq]);
                bfr[1] = __float_as_uint(Vs[(kt8 * 8 + jp + 4) * VSTR + dn * 8 + qq]);
                mma_tf32(oacc[dn], pa, bfr);
            }
        }

        __syncthreads();
        if (t + 2 < nkt) {
            load_kv(t + 2, buf);
            CP_WAIT(1);
        } else {
            CP_WAIT(0);
        }
        __syncthreads();
    }

    // ---- epilogue: normalize, write z ----
    float inv0 = 1.f / l0, inv1 = 1.f / l1;
    float* zp0 = g_z + (size_t)(b * SEQ + row0) * DM + head * HD;
    float* zp8 = zp0 + (size_t)8 * DM;
#pragma unroll
    for (int dn = 0; dn < 8; dn++) {
        int col = dn * 8 + 2 * jp;
        float2 o0, o1;
        o0.x = oacc[dn][0] * inv0; o0.y = oacc[dn][1] * inv0;
        o1.x = oacc[dn][2] * inv1; o1.y = oacc[dn][3] * inv1;
        *(float2*)(zp0 + col) = o0;
        *(float2*)(zp8 + col) = o1;
    }
}

// ---------------------------------------------------------------------------
extern "C" void kernel_launch(void* const* d_in, const int* in_sizes, int n_in,
                              void* d_out, int out_size) {
    const float* x  = (const float*)d_in[0];
    const float* WQ = (const float*)d_in[1];
    const float* WK = (const float*)d_in[2];
    const float* WV = (const float*)d_in[3];
    const float* WO = (const float*)d_in[4];
    const float* bQ = (const float*)d_in[5];
    const float* bK = (const float*)d_in[6];
    const float* bV = (const float*)d_in[7];
    const float* bO = (const float*)d_in[8];
    float* out = (float*)d_out;

    float *wqkvT, *woT, *bqkv, *qkv, *z;
    cudaGetSymbolAddress((void**)&wqkvT, g_wqkvT);
    cudaGetSymbolAddress((void**)&woT,   g_woT);
    cudaGetSymbolAddress((void**)&bqkv,  g_bqkv);
    cudaGetSymbolAddress((void**)&qkv,   g_qkv);
    cudaGetSymbolAddress((void**)&z,     g_z);

    cudaFuncSetAttribute(gemm_mma_kernel,
                         cudaFuncAttributeMaxDynamicSharedMemorySize, GEMM_SMEM);
    cudaFuncSetAttribute(attn_mma_kernel,
                         cudaFuncAttributeMaxDynamicSharedMemorySize, ATT_SMEM);

    // 1) pack weights (transposed, tf32-rounded) + bias
    pack_w_kernel<<<(QKVC * DM + 255) / 256, 256>>>(WQ, WK, WV, WO, bQ, bK, bV);

    // 2) QKV projection (tf32 mma.sync)
    {
        dim3 grid(QKVC / BN, TOK / BM);
        gemm_mma_kernel<<<grid, 256, GEMM_SMEM>>>(x, wqkvT, bqkv, qkv, QKVC);
    }

    // 3) causal flash attention (tf32 mma.sync) -> z
    {
        dim3 grid(SEQ / AQ, NHEADS, BATCH);
        attn_mma_kernel<<<grid, 256, ATT_SMEM>>>();
    }

    // 4) output projection (tf32 mma.sync)
    {
        dim3 grid(DM / BN, TOK / BM);
        gemm_mma_kernel<<<grid, 256, GEMM_SMEM>>>(z, woT, bO, out, DM);
    }
}

// round 6
// speedup vs baseline: 3.6326x; 1.0654x over previous
#include <cuda_runtime.h>
#include <cstdint>

#define BATCH  4
#define SEQ    2048
#define DM     768
#define NHEADS 12
#define HD     64
#define TOK    (BATCH * SEQ)     // 8192
#define QKVC   (3 * DM)          // 2304

// ---------------- scratch (device globals; allocation-free) ----------------
__device__ float g_wqkvT[(size_t)QKVC * DM];   // B^T (tf32-rounded): [2304][768]
__device__ float g_woT[(size_t)DM * DM];       // B^T (tf32-rounded): [768][768]
__device__ float g_bqkv[QKVC];
__device__ float g_qkv[(size_t)TOK * QKVC];    // q|k|v per token
__device__ float g_z[(size_t)TOK * DM];

// ---------------------------- PTX helpers ----------------------------------
__device__ __forceinline__ uint32_t smem_u32(const void* p) {
    uint32_t a;
    asm("{ .reg .u64 t; cvta.to.shared.u64 t, %1; cvt.u32.u64 %0, t; }"
        : "=r"(a) : "l"(p));
    return a;
}
__device__ __forceinline__ void cpa16(uint32_t s, const void* g) {
    asm volatile("cp.async.cg.shared.global [%0], [%1], 16;" :: "r"(s), "l"(g));
}
#define CP_COMMIT() asm volatile("cp.async.commit_group;" ::: "memory")
#define CP_WAIT(n)  asm volatile("cp.async.wait_group %0;" :: "n"(n) : "memory")

__device__ __forceinline__ uint32_t f2tf32(float f) {
    uint32_t r;
    asm("cvt.rna.tf32.f32 %0, %1;" : "=r"(r) : "f"(f));
    return r;
}
__device__ __forceinline__ void mma_tf32(float* d, const uint32_t* a,
                                         const uint32_t* b) {
    asm volatile(
        "mma.sync.aligned.m16n8k8.row.col.f32.tf32.tf32.f32 "
        "{%0,%1,%2,%3}, {%4,%5,%6,%7}, {%8,%9}, {%0,%1,%2,%3};"
        : "+f"(d[0]), "+f"(d[1]), "+f"(d[2]), "+f"(d[3])
        : "r"(a[0]), "r"(a[1]), "r"(a[2]), "r"(a[3]), "r"(b[0]), "r"(b[1]));
}

// ---------------------------------------------------------------------------
// Pack: transpose weights into K-major B^T (rounded to tf32) + pack qkv bias
// ---------------------------------------------------------------------------
__global__ void pack_w_kernel(const float* __restrict__ WQ,
                              const float* __restrict__ WK,
                              const float* __restrict__ WV,
                              const float* __restrict__ WO,
                              const float* __restrict__ bQ,
                              const float* __restrict__ bK,
                              const float* __restrict__ bV) {
    int idx = blockIdx.x * blockDim.x + threadIdx.x;
    if (idx < QKVC * DM) {
        int c = idx / DM;
        int e = idx - c * DM;
        int p = c / DM;
        int nh = c - p * DM;
        const float* W = (p == 0) ? WQ : (p == 1) ? WK : WV;
        int n = nh / HD;
        int h = nh - n * HD;
        g_wqkvT[idx] = __uint_as_float(f2tf32(W[((size_t)n * DM + e) * HD + h]));
    }
    if (idx < DM * DM) {
        int e = idx / DM;
        int nh = idx - e * DM;
        g_woT[idx] = __uint_as_float(f2tf32(WO[(size_t)nh * DM + e]));
    }
    if (idx < QKVC) {
        int p = idx / DM;
        int nh = idx - p * DM;
        const float* bb = (p == 0) ? bQ : (p == 1) ? bK : bV;
        g_bqkv[idx] = bb[nh];
    }
}

// ---------------------------------------------------------------------------
// TF32 mma.sync GEMM v2:  C[M,N] = A[M,768] * Bt[N,768]^T + bias[N]
// Block 128x128, 128 threads (4 warps as 2x2), warp tile 64x64 (4x8 m16n8k8).
// BK=32, cp.async double-buffered. Smem stride 36 floats (conflict-free).
// ---------------------------------------------------------------------------
#define BM 128
#define BN 128
#define BK 32
#define STR 36
#define NCHUNK (DM / BK)
#define BUF_FLOATS (2 * BM * STR)        // 9216 floats (A + B tile)
#define GEMM_SMEM (2 * BUF_FLOATS * 4)   // 73728 bytes

__global__ __launch_bounds__(128, 2)
void gemm_mma_kernel(const float* __restrict__ A, const float* __restrict__ Bt,
                     const float* __restrict__ bias, float* __restrict__ C,
                     int N) {
    extern __shared__ float smem[];
    uint32_t sb = smem_u32(smem);
    int tid = threadIdx.x;
    int lane = tid & 31;
    int wid = tid >> 5;
    int qq = lane >> 2;
    int jp = lane & 3;
    int warpM = wid & 1;          // 2 along M
    int warpN = wid >> 1;         // 2 along N
    int m0 = blockIdx.y * BM;
    int n0 = blockIdx.x * BN;

    auto load_chunk = [&](int c, int buf) {
        uint32_t abase = sb + buf * (BUF_FLOATS * 4);
        uint32_t bbase = abase + BM * STR * 4;
        int k0 = c * BK;
        const float* ap = A + (size_t)m0 * DM + k0;
        const float* bp = Bt + (size_t)n0 * DM + k0;
#pragma unroll
        for (int it = 0; it < 8; it++) {
            int t = tid + it * 128;
            int row = t >> 3, seg = t & 7;
            cpa16(abase + row * (STR * 4) + seg * 16,
                  ap + (size_t)row * DM + seg * 4);
        }
#pragma unroll
        for (int it = 0; it < 8; it++) {
            int t = tid + it * 128;
            int row = t >> 3, seg = t & 7;
            cpa16(bbase + row * (STR * 4) + seg * 16,
                  bp + (size_t)row * DM + seg * 4);
        }
        CP_COMMIT();
    };

    float acc[4][8][4];
#pragma unroll
    for (int mi = 0; mi < 4; mi++)
#pragma unroll
        for (int ni = 0; ni < 8; ni++)
#pragma unroll
            for (int j = 0; j < 4; j++) acc[mi][ni][j] = 0.f;

    load_chunk(0, 0);
    load_chunk(1, 1);
    CP_WAIT(1);
    __syncthreads();

    int r0 = warpM * 64 + qq;
    int c0 = warpN * 64 + qq;

    for (int c = 0; c < NCHUNK; c++) {
        int buf = c & 1;
        const float* As = smem + buf * BUF_FLOATS;
        const float* Bs = As + BM * STR;
#pragma unroll
        for (int ks = 0; ks < 4; ks++) {
            int kc = ks * 8 + jp;
            uint32_t a[4][4], b[8][2];
#pragma unroll
            for (int mi = 0; mi < 4; mi++) {
                int base = (r0 + mi * 16) * STR + kc;
                a[mi][0] = f2tf32(As[base]);
                a[mi][1] = f2tf32(As[base + 8 * STR]);
                a[mi][2] = f2tf32(As[base + 4]);
                a[mi][3] = f2tf32(As[base + 8 * STR + 4]);
            }
#pragma unroll
            for (int ni = 0; ni < 8; ni++) {
                int bb = (c0 + ni * 8) * STR + kc;
                b[ni][0] = __float_as_uint(Bs[bb]);
                b[ni][1] = __float_as_uint(Bs[bb + 4]);
            }
#pragma unroll
            for (int mi = 0; mi < 4; mi++)
#pragma unroll
                for (int ni = 0; ni < 8; ni++)
                    mma_tf32(acc[mi][ni], a[mi], b[ni]);
        }
        __syncthreads();
        if (c + 2 < NCHUNK) {
            load_chunk(c + 2, buf);
            CP_WAIT(1);
        } else {
            CP_WAIT(0);
        }
        __syncthreads();
    }

#pragma unroll
    for (int mi = 0; mi < 4; mi++)
#pragma unroll
        for (int h = 0; h < 2; h++) {
            int row = m0 + warpM * 64 + mi * 16 + qq + h * 8;
#pragma unroll
            for (int ni = 0; ni < 8; ni++) {
                int col = n0 + warpN * 64 + ni * 8 + jp * 2;
                float2 bv = *(const float2*)(bias + col);
                float2 o;
                o.x = acc[mi][ni][h * 2 + 0] + bv.x;
                o.y = acc[mi][ni][h * 2 + 1] + bv.y;
                *(float2*)(C + (size_t)row * N + col) = o;
            }
        }
}

// ---------------------------------------------------------------------------
// Flash attention with tf32 mma.sync (v2).
// Q staged in smem (frees 32 regs -> no spills at 2 CTAs). exp2-domain
// softmax (scale*log2e folded into mask step). K-tile 64, double-buffered.
// ---------------------------------------------------------------------------
#define AQ 128
#define AK 64
#define QSTR 68
#define KSTR 68
#define VSTR 72
#define Q_FLOATS (AQ * QSTR)                    // 8704
#define ATT_BUF (AK * KSTR + AK * VSTR)         // 8960 floats
#define ATT_SMEM ((Q_FLOATS + 2 * ATT_BUF) * 4) // 106496 bytes

__global__ __launch_bounds__(256, 2)
void attn_mma_kernel() {
    extern __shared__ float smem[];
    uint32_t sb = smem_u32(smem);
    int tid = threadIdx.x;
    int lane = tid & 31;
    int wid = tid >> 5;
    int qq = lane >> 2;
    int jp = lane & 3;

    int qi = gridDim.x - 1 - blockIdx.x;   // heavy blocks first
    int head = blockIdx.y, b = blockIdx.z;
    int q0 = qi * AQ;
    int nkt = 2 * qi + 2;

    const float* Qs = smem;

    // ---- stage Q tile into smem (cp.async, grouped with first KV tile) ----
    {
        const float* qsrc = g_qkv + (size_t)(b * SEQ + q0) * QKVC + head * HD;
#pragma unroll
        for (int it = 0; it < 8; it++) {
            int s = tid + it * 256;
            int row = s >> 4, seg = s & 15;
            cpa16(sb + row * (QSTR * 4) + seg * 16,
                  qsrc + (size_t)row * QKVC + seg * 4);
        }
    }

    auto load_kv = [&](int t, int buf) {
        int k0 = t * AK;
        uint32_t kb = sb + (Q_FLOATS + buf * ATT_BUF) * 4;
        uint32_t vb = kb + AK * KSTR * 4;
#pragma unroll
        for (int it = 0; it < 4; it++) {
            int s = tid + it * 256;
            int row = s >> 4, seg = s & 15;
            size_t src = (size_t)(b * SEQ + k0 + row) * QKVC + head * HD + seg * 4;
            cpa16(kb + row * (KSTR * 4) + seg * 16, g_qkv + DM + src);
        }
#pragma unroll
        for (int it = 0; it < 4; it++) {
            int s = tid + it * 256;
            int row = s >> 4, seg = s & 15;
            size_t src = (size_t)(b * SEQ + k0 + row) * QKVC + head * HD + seg * 4;
            cpa16(vb + row * (VSTR * 4) + seg * 16, g_qkv + 2 * DM + src);
        }
        CP_COMMIT();
    };

    float oacc[8][4];
#pragma unroll
    for (int dn = 0; dn < 8; dn++)
#pragma unroll
        for (int j = 0; j < 4; j++) oacc[dn][j] = 0.f;
    float m0 = -1e30f, m1 = -1e30f, l0 = 0.f, l1 = 0.f;

    load_kv(0, 0);          // commits {Q, KV0} as one group
    load_kv(1, 1);
    CP_WAIT(1);
    __syncthreads();

    const float scale2 = 0.18033688f;   // (1/sqrt(64)) * log2(e)
    int row0 = q0 + wid * 16 + qq;
    int qrow = (wid * 16 + qq) * QSTR;

    for (int t = 0; t < nkt; t++) {
        int buf = t & 1;
        int k0 = t * AK;
        const float* Ks = smem + Q_FLOATS + buf * ATT_BUF;
        const float* Vs = Ks + AK * KSTR;

        // ---- S = Q @ K^T ----
        float facc[8][4];
#pragma unroll
        for (int nf = 0; nf < 8; nf++)
#pragma unroll
            for (int j = 0; j < 4; j++) facc[nf][j] = 0.f;
#pragma unroll
        for (int ks = 0; ks < 8; ks++) {
            int kc = ks * 8 + jp;
            uint32_t qa[4];
            qa[0] = f2tf32(Qs[qrow + kc]);
            qa[1] = f2tf32(Qs[qrow + 8 * QSTR + kc]);
            qa[2] = f2tf32(Qs[qrow + kc + 4]);
            qa[3] = f2tf32(Qs[qrow + 8 * QSTR + kc + 4]);
#pragma unroll
            for (int nf = 0; nf < 8; nf++) {
                uint32_t bfr[2];
                bfr[0] = __float_as_uint(Ks[(nf * 8 + qq) * KSTR + kc]);
                bfr[1] = __float_as_uint(Ks[(nf * 8 + qq) * KSTR + kc + 4]);
                mma_tf32(facc[nf], qa, bfr);
            }
        }

        // ---- scale (log2 domain) + causal mask ----
        bool diag = (t >= nkt - 2);
#pragma unroll
        for (int nf = 0; nf < 8; nf++) {
            int kg = k0 + nf * 8 + 2 * jp;
#pragma unroll
            for (int e = 0; e < 4; e++) {
                int col = kg + (e & 1);
                int row = row0 + ((e >= 2) ? 8 : 0);
                float v = facc[nf][e] * scale2;
                if (diag && col > row) v = -1e30f;
                facc[nf][e] = v;
            }
        }

        // ---- online softmax (base-2) ----
        float mx0 = -1e30f, mx1 = -1e30f;
#pragma unroll
        for (int nf = 0; nf < 8; nf++) {
            mx0 = fmaxf(mx0, fmaxf(facc[nf][0], facc[nf][1]));
            mx1 = fmaxf(mx1, fmaxf(facc[nf][2], facc[nf][3]));
        }
        mx0 = fmaxf(mx0, __shfl_xor_sync(0xffffffffu, mx0, 1));
        mx0 = fmaxf(mx0, __shfl_xor_sync(0xffffffffu, mx0, 2));
        mx1 = fmaxf(mx1, __shfl_xor_sync(0xffffffffu, mx1, 1));
        mx1 = fmaxf(mx1, __shfl_xor_sync(0xffffffffu, mx1, 2));
        float nm0 = fmaxf(m0, mx0), nm1 = fmaxf(m1, mx1);
        float al0 = exp2f(m0 - nm0), al1 = exp2f(m1 - nm1);
        m0 = nm0; m1 = nm1;
        float rs0 = 0.f, rs1 = 0.f;
#pragma unroll
        for (int nf = 0; nf < 8; nf++) {
            facc[nf][0] = exp2f(facc[nf][0] - nm0);
            facc[nf][1] = exp2f(facc[nf][1] - nm0);
            facc[nf][2] = exp2f(facc[nf][2] - nm1);
            facc[nf][3] = exp2f(facc[nf][3] - nm1);
            rs0 += facc[nf][0] + facc[nf][1];
            rs1 += facc[nf][2] + facc[nf][3];
        }
        rs0 += __shfl_xor_sync(0xffffffffu, rs0, 1);
        rs0 += __shfl_xor_sync(0xffffffffu, rs0, 2);
        rs1 += __shfl_xor_sync(0xffffffffu, rs1, 1);
        rs1 += __shfl_xor_sync(0xffffffffu, rs1, 2);
        l0 = l0 * al0 + rs0;
        l1 = l1 * al1 + rs1;
#pragma unroll
        for (int dn = 0; dn < 8; dn++) {
            oacc[dn][0] *= al0; oacc[dn][1] *= al0;
            oacc[dn][2] *= al1; oacc[dn][3] *= al1;
        }

        // ---- O += P @ V : transpose P acc->A-frag via shfl ----
        int srcA = (lane & 28) | (jp >> 1);
        bool odd = jp & 1;
#pragma unroll
        for (int kt8 = 0; kt8 < 8; kt8++) {
            uint32_t pc0 = f2tf32(facc[kt8][0]);
            uint32_t pc1 = f2tf32(facc[kt8][1]);
            uint32_t pc2 = f2tf32(facc[kt8][2]);
            uint32_t pc3 = f2tf32(facc[kt8][3]);
            uint32_t s0 = __shfl_sync(0xffffffffu, pc0, srcA);
            uint32_t s1 = __shfl_sync(0xffffffffu, pc1, srcA);
            uint32_t s2 = __shfl_sync(0xffffffffu, pc2, srcA);
            uint32_t s3 = __shfl_sync(0xffffffffu, pc3, srcA);
            uint32_t u0 = __shfl_sync(0xffffffffu, pc0, srcA + 2);
            uint32_t u1 = __shfl_sync(0xffffffffu, pc1, srcA + 2);
            uint32_t u2 = __shfl_sync(0xffffffffu, pc2, srcA + 2);
            uint32_t u3 = __shfl_sync(0xffffffffu, pc3, srcA + 2);
            uint32_t pa[4];
            pa[0] = odd ? s1 : s0;
            pa[1] = odd ? s3 : s2;
            pa[2] = odd ? u1 : u0;
            pa[3] = odd ? u3 : u2;
#pragma unroll
            for (int dn = 0; dn < 8; dn++) {
                uint32_t bfr[2];
                bfr[0] = __float_as_uint(Vs[(kt8 * 8 + jp) * VSTR + dn * 8 + qq]);
                bfr[1] = __float_as_uint(Vs[(kt8 * 8 + jp + 4) * VSTR + dn * 8 + qq]);
                mma_tf32(oacc[dn], pa, bfr);
            }
        }

        __syncthreads();
        if (t + 2 < nkt) {
            load_kv(t + 2, buf);
            CP_WAIT(1);
        } else {
            CP_WAIT(0);
        }
        __syncthreads();
    }

    // ---- epilogue: normalize, write z ----
    float inv0 = 1.f / l0, inv1 = 1.f / l1;
    float* zp0 = g_z + (size_t)(b * SEQ + row0) * DM + head * HD;
    float* zp8 = zp0 + (size_t)8 * DM;
#pragma unroll
    for (int dn = 0; dn < 8; dn++) {
        int col = dn * 8 + 2 * jp;
        float2 o0, o1;
        o0.x = oacc[dn][0] * inv0; o0.y = oacc[dn][1] * inv0;
        o1.x = oacc[dn][2] * inv1; o1.y = oacc[dn][3] * inv1;
        *(float2*)(zp0 + col) = o0;
        *(float2*)(zp8 + col) = o1;
    }
}

// ---------------------------------------------------------------------------
extern "C" void kernel_launch(void* const* d_in, const int* in_sizes, int n_in,
                              void* d_out, int out_size) {
    const float* x  = (const float*)d_in[0];
    const float* WQ = (const float*)d_in[1];
    const float* WK = (const float*)d_in[2];
    const float* WV = (const float*)d_in[3];
    const float* WO = (const float*)d_in[4];
    const float* bQ = (const float*)d_in[5];
    const float* bK = (const float*)d_in[6];
    const float* bV = (const float*)d_in[7];
    const float* bO = (const float*)d_in[8];
    float* out = (float*)d_out;

    float *wqkvT, *woT, *bqkv, *qkv, *z;
    cudaGetSymbolAddress((void**)&wqkvT, g_wqkvT);
    cudaGetSymbolAddress((void**)&woT,   g_woT);
    cudaGetSymbolAddress((void**)&bqkv,  g_bqkv);
    cudaGetSymbolAddress((void**)&qkv,   g_qkv);
    cudaGetSymbolAddress((void**)&z,     g_z);

    cudaFuncSetAttribute(gemm_mma_kernel,
                         cudaFuncAttributeMaxDynamicSharedMemorySize, GEMM_SMEM);
    cudaFuncSetAttribute(attn_mma_kernel,
                         cudaFuncAttributeMaxDynamicSharedMemorySize, ATT_SMEM);

    // 1) pack weights (transposed, tf32-rounded) + bias
    pack_w_kernel<<<(QKVC * DM + 255) / 256, 256>>>(WQ, WK, WV, WO, bQ, bK, bV);

    // 2) QKV projection (tf32 mma.sync)
    {
        dim3 grid(QKVC / BN, TOK / BM);
        gemm_mma_kernel<<<grid, 128, GEMM_SMEM>>>(x, wqkvT, bqkv, qkv, QKVC);
    }

    // 3) causal flash attention (tf32 mma.sync) -> z
    {
        dim3 grid(SEQ / AQ, NHEADS, BATCH);
        attn_mma_kernel<<<grid, 256, ATT_SMEM>>>();
    }

    // 4) output projection (tf32 mma.sync)
    {
        dim3 grid(DM / BN, TOK / BM);
        gemm_mma_kernel<<<grid, 128, GEMM_SMEM>>>(z, woT, bO, out, DM);
    }
}

// round 8
// speedup vs baseline: 4.0744x; 1.1216x over previous
#include <cuda_runtime.h>
#include <cstdint>

#define BATCH  4
#define SEQ    2048
#define DM     768
#define NHEADS 12
#define HD     64
#define TOK    (BATCH * SEQ)     // 8192
#define QKVC   (3 * DM)          // 2304

// ---------------- scratch (device globals; allocation-free) ----------------
__device__ float g_xr[(size_t)TOK * DM];       // x rounded to tf32
__device__ float g_wqkvT[(size_t)QKVC * DM];   // B^T, k-interleaved, tf32
__device__ float g_woT[(size_t)DM * DM];       // B^T, k-interleaved, tf32
__device__ float g_bqkv[QKVC];
__device__ float g_qkv[(size_t)TOK * QKVC];    // q|k|v per token (tf32-rounded)
__device__ float g_z[(size_t)TOK * DM];        // attn out (tf32-rounded)

// ---------------------------- PTX helpers ----------------------------------
__device__ __forceinline__ uint32_t smem_u32(const void* p) {
    uint32_t a;
    asm("{ .reg .u64 t; cvta.to.shared.u64 t, %1; cvt.u32.u64 %0, t; }"
        : "=r"(a) : "l"(p));
    return a;
}
__device__ __forceinline__ void cpa16(uint32_t s, const void* g) {
    asm volatile("cp.async.cg.shared.global [%0], [%1], 16;" :: "r"(s), "l"(g));
}
#define CP_COMMIT() asm volatile("cp.async.commit_group;" ::: "memory")
#define CP_WAIT(n)  asm volatile("cp.async.wait_group %0;" :: "n"(n) : "memory")

__device__ __forceinline__ uint32_t f2tf32(float f) {
    uint32_t r;
    asm("cvt.rna.tf32.f32 %0, %1;" : "=r"(r) : "f"(f));
    return r;
}
__device__ __forceinline__ float rnd(float f) {
    return __uint_as_float(f2tf32(f));
}
__device__ __forceinline__ float ex2(float x) {
    float y;
    asm("ex2.approx.ftz.f32 %0, %1;" : "=f"(y) : "f"(x));
    return y;
}
__device__ __forceinline__ void mma_tf32(float* d, const uint32_t* a,
                                         const uint32_t* b) {
    asm volatile(
        "mma.sync.aligned.m16n8k8.row.col.f32.tf32.tf32.f32 "
        "{%0,%1,%2,%3}, {%4,%5,%6,%7}, {%8,%9}, {%0,%1,%2,%3};"
        : "+f"(d[0]), "+f"(d[1]), "+f"(d[2]), "+f"(d[3])
        : "r"(a[0]), "r"(a[1]), "r"(a[2]), "r"(a[3]), "r"(b[0]), "r"(b[1]));
}
// permuted k-position -> original k (within 8-group interleave)
__device__ __forceinline__ int kperm(int kp) {
    return (kp & ~7) | (((kp & 7) >> 1) + ((kp & 1) << 2));
}

// ---------------------------------------------------------------------------
// Round x -> tf32 copy (float4)
// ---------------------------------------------------------------------------
__global__ void round_x_kernel(const float* __restrict__ x) {
    int i = blockIdx.x * blockDim.x + threadIdx.x;
    float4 v = *(const float4*)(x + (size_t)i * 4);
    v.x = rnd(v.x); v.y = rnd(v.y); v.z = rnd(v.z); v.w = rnd(v.w);
    *(float4*)(g_xr + (size_t)i * 4) = v;
}

// ---------------------------------------------------------------------------
// Pack: weights -> K-major B^T, k-interleaved within 8-groups, tf32-rounded
// ---------------------------------------------------------------------------
__global__ void pack_w_kernel(const float* __restrict__ WQ,
                              const float* __restrict__ WK,
                              const float* __restrict__ WV,
                              const float* __restrict__ WO,
                              const float* __restrict__ bQ,
                              const float* __restrict__ bK,
                              const float* __restrict__ bV) {
    int idx = blockIdx.x * blockDim.x + threadIdx.x;
    if (idx < QKVC * DM) {
        int c = idx / DM;              // output column 0..2303
        int kp = idx - c * DM;         // permuted k position
        int e = kperm(kp);             // original model-dim index
        int p = c / DM;
        int nh = c - p * DM;
        const float* W = (p == 0) ? WQ : (p == 1) ? WK : WV;
        int n = nh / HD;
        int h = nh - n * HD;
        g_wqkvT[idx] = rnd(W[((size_t)n * DM + e) * HD + h]);
    }
    if (idx < DM * DM) {
        int e = idx / DM;              // output column (model dim)
        int kp = idx - e * DM;         // permuted k position (= nh)
        int nh = kperm(kp);
        g_woT[idx] = rnd(WO[(size_t)nh * DM + e]);
    }
    if (idx < QKVC) {
        int p = idx / DM;
        int nh = idx - p * DM;
        const float* bb = (p == 0) ? bQ : (p == 1) ? bK : bV;
        g_bqkv[idx] = bb[nh];
    }
}

// ---------------------------------------------------------------------------
// TF32 mma.sync GEMM v3:  C[M,N] = A[M,768] * Bt[N,768]^T + bias[N]
// Block 128x128, 128 threads (2x2 warps), warp tile 64x64.
// A: pre-rounded tf32, scalar LDS, stride 36.
// B: pre-rounded + k-interleaved -> LDS.64 pairs, stride 40.
// ROUND_OUT: round outputs to tf32 (for tensors feeding another mma).
// ---------------------------------------------------------------------------
#define BM 128
#define BN 128
#define BK 32
#define ASTR 36
#define BSTR 40
#define NCHUNK (DM / BK)
#define A_FLOATS (BM * ASTR)                 // 4608
#define B_FLOATS (BN * BSTR)                 // 5120
#define BUF_FLOATS (A_FLOATS + B_FLOATS)     // 9728
#define GEMM_SMEM (2 * BUF_FLOATS * 4)       // 77824 bytes

template <bool ROUND_OUT>
__global__ __launch_bounds__(128, 2)
void gemm_mma_kernel(const float* __restrict__ A, const float* __restrict__ Bt,
                     const float* __restrict__ bias, float* __restrict__ C,
                     int N) {
    extern __shared__ float smem[];
    uint32_t sb = smem_u32(smem);
    int tid = threadIdx.x;
    int lane = tid & 31;
    int wid = tid >> 5;
    int qq = lane >> 2;
    int jp = lane & 3;
    int warpM = wid & 1;
    int warpN = wid >> 1;
    int m0 = blockIdx.y * BM;
    int n0 = blockIdx.x * BN;

    auto load_chunk = [&](int c, int buf) {
        uint32_t abase = sb + buf * (BUF_FLOATS * 4);
        uint32_t bbase = abase + A_FLOATS * 4;
        int k0 = c * BK;
        const float* ap = A + (size_t)m0 * DM + k0;
        const float* bp = Bt + (size_t)n0 * DM + k0;
#pragma unroll
        for (int it = 0; it < 8; it++) {
            int t = tid + it * 128;
            int row = t >> 3, seg = t & 7;
            cpa16(abase + row * (ASTR * 4) + seg * 16,
                  ap + (size_t)row * DM + seg * 4);
        }
#pragma unroll
        for (int it = 0; it < 8; it++) {
            int t = tid + it * 128;
            int row = t >> 3, seg = t & 7;
            cpa16(bbase + row * (BSTR * 4) + seg * 16,
                  bp + (size_t)row * DM + seg * 4);
        }
        CP_COMMIT();
    };

    float acc[4][8][4];
#pragma unroll
    for (int mi = 0; mi < 4; mi++)
#pragma unroll
        for (int ni = 0; ni < 8; ni++)
#pragma unroll
            for (int j = 0; j < 4; j++) acc[mi][ni][j] = 0.f;

    load_chunk(0, 0);
    load_chunk(1, 1);
    CP_WAIT(1);
    __syncthreads();

    int r0 = warpM * 64 + qq;
    int c0 = warpN * 64 + qq;

    for (int c = 0; c < NCHUNK; c++) {
        int buf = c & 1;
        const float* As = smem + buf * BUF_FLOATS;
        const float* Bs = As + A_FLOATS;
#pragma unroll
        for (int ks = 0; ks < 4; ks++) {
            int kc = ks * 8 + jp;
            uint32_t a[4][4], b[8][2];
#pragma unroll
            for (int mi = 0; mi < 4; mi++) {
                int base = (r0 + mi * 16) * ASTR + kc;
                a[mi][0] = __float_as_uint(As[base]);
                a[mi][1] = __float_as_uint(As[base + 8 * ASTR]);
                a[mi][2] = __float_as_uint(As[base + 4]);
                a[mi][3] = __float_as_uint(As[base + 8 * ASTR + 4]);
            }
#pragma unroll
            for (int ni = 0; ni < 8; ni++) {
                float2 bp2 = *(const float2*)&Bs[(c0 + ni * 8) * BSTR
                                                 + ks * 8 + 2 * jp];
                b[ni][0] = __float_as_uint(bp2.x);
                b[ni][1] = __float_as_uint(bp2.y);
            }
#pragma unroll
            for (int mi = 0; mi < 4; mi++)
#pragma unroll
                for (int ni = 0; ni < 8; ni++)
                    mma_tf32(acc[mi][ni], a[mi], b[ni]);
        }
        __syncthreads();
        if (c + 2 < NCHUNK) {
            load_chunk(c + 2, buf);
            CP_WAIT(1);
        } else {
            CP_WAIT(0);
        }
        __syncthreads();
    }

#pragma unroll
    for (int mi = 0; mi < 4; mi++)
#pragma unroll
        for (int h = 0; h < 2; h++) {
            int row = m0 + warpM * 64 + mi * 16 + qq + h * 8;
#pragma unroll
            for (int ni = 0; ni < 8; ni++) {
                int col = n0 + warpN * 64 + ni * 8 + jp * 2;
                float2 bv = *(const float2*)(bias + col);
                float2 o;
                o.x = acc[mi][ni][h * 2 + 0] + bv.x;
                o.y = acc[mi][ni][h * 2 + 1] + bv.y;
                if (ROUND_OUT) { o.x = rnd(o.x); o.y = rnd(o.y); }
                *(float2*)(C + (size_t)row * N + col) = o;
            }
        }
}

// ---------------------------------------------------------------------------
// Flash attention v3 (tf32 mma.sync).
// 128 threads, 4 warps; warp tile 32x64 (2 m16 tiles share K/V b-frags).
// Q/K/V pre-rounded by QKV gemm epilogue -> raw-bit loads everywhere.
// ex2.approx softmax, P frags cvt.rna. z output rounded for out-proj.
// ---------------------------------------------------------------------------
#define AQ 128
#define AK 64
#define QSTR 68
#define KSTR 68
#define VSTR 72
#define Q_FLOATS (AQ * QSTR)                    // 8704
#define ATT_BUF (AK * KSTR + AK * VSTR)         // 8960 floats
#define ATT_SMEM ((Q_FLOATS + 2 * ATT_BUF) * 4) // 106496 bytes

__global__ __launch_bounds__(128, 2)
void attn_mma_kernel() {
    extern __shared__ float smem[];
    uint32_t sb = smem_u32(smem);
    int tid = threadIdx.x;
    int lane = tid & 31;
    int wid = tid >> 5;
    int qq = lane >> 2;
    int jp = lane & 3;

    int qi = gridDim.x - 1 - blockIdx.x;   // heavy blocks first
    int head = blockIdx.y, b = blockIdx.z;
    int q0 = qi * AQ;
    int nkt = 2 * qi + 2;

    const float* Qs = smem;

    // ---- stage Q tile into smem ----
    {
        const float* qsrc = g_qkv + (size_t)(b * SEQ + q0) * QKVC + head * HD;
#pragma unroll
        for (int it = 0; it < 16; it++) {
            int s = tid + it * 128;
            int row = s >> 4, seg = s & 15;
            cpa16(sb + row * (QSTR * 4) + seg * 16,
                  qsrc + (size_t)row * QKVC + seg * 4);
        }
    }

    auto load_kv = [&](int t, int buf) {
        int k0 = t * AK;
        uint32_t kb = sb + (Q_FLOATS + buf * ATT_BUF) * 4;
        uint32_t vb = kb + AK * KSTR * 4;
#pragma unroll
        for (int it = 0; it < 8; it++) {
            int s = tid + it * 128;
            int row = s >> 4, seg = s & 15;
            size_t src = (size_t)(b * SEQ + k0 + row) * QKVC + head * HD + seg * 4;
            cpa16(kb + row * (KSTR * 4) + seg * 16, g_qkv + DM + src);
        }
#pragma unroll
        for (int it = 0; it < 8; it++) {
            int s = tid + it * 128;
            int row = s >> 4, seg = s & 15;
            size_t src = (size_t)(b * SEQ + k0 + row) * QKVC + head * HD + seg * 4;
            cpa16(vb + row * (VSTR * 4) + seg * 16, g_qkv + 2 * DM + src);
        }
        CP_COMMIT();
    };

    float oacc[2][8][4];
#pragma unroll
    for (int mi = 0; mi < 2; mi++)
#pragma unroll
        for (int dn = 0; dn < 8; dn++)
#pragma unroll
            for (int j = 0; j < 4; j++) oacc[mi][dn][j] = 0.f;
    float mm[2][2], ll[2][2];
#pragma unroll
    for (int mi = 0; mi < 2; mi++) {
        mm[mi][0] = -1e30f; mm[mi][1] = -1e30f;
        ll[mi][0] = 0.f;    ll[mi][1] = 0.f;
    }

    load_kv(0, 0);
    load_kv(1, 1);
    CP_WAIT(1);
    __syncthreads();

    const float scale2 = 0.18033688f;   // (1/sqrt(64)) * log2(e)
    int rbase = q0 + wid * 32 + qq;     // mi adds 16

    for (int t = 0; t < nkt; t++) {
        int buf = t & 1;
        int k0 = t * AK;
        const float* Ks = smem + Q_FLOATS + buf * ATT_BUF;
        const float* Vs = Ks + AK * KSTR;

        // ---- S = Q @ K^T (2 m-tiles share K b-frags) ----
        float facc[2][8][4];
#pragma unroll
        for (int mi = 0; mi < 2; mi++)
#pragma unroll
            for (int nf = 0; nf < 8; nf++)
#pragma unroll
                for (int j = 0; j < 4; j++) facc[mi][nf][j] = 0.f;
#pragma unroll
        for (int ks = 0; ks < 8; ks++) {
            int kc = ks * 8 + jp;
            uint32_t qa[2][4];
#pragma unroll
            for (int mi = 0; mi < 2; mi++) {
                int base = (wid * 32 + mi * 16 + qq) * QSTR + kc;
                qa[mi][0] = __float_as_uint(Qs[base]);
                qa[mi][1] = __float_as_uint(Qs[base + 8 * QSTR]);
                qa[mi][2] = __float_as_uint(Qs[base + 4]);
                qa[mi][3] = __float_as_uint(Qs[base + 8 * QSTR + 4]);
            }
#pragma unroll
            for (int nf = 0; nf < 8; nf++) {
                uint32_t bfr[2];
                bfr[0] = __float_as_uint(Ks[(nf * 8 + qq) * KSTR + kc]);
                bfr[1] = __float_as_uint(Ks[(nf * 8 + qq) * KSTR + kc + 4]);
                mma_tf32(facc[0][nf], qa[0], bfr);
                mma_tf32(facc[1][nf], qa[1], bfr);
            }
        }

        // ---- scale (log2 domain) + causal mask + online softmax ----
        bool diag = (t >= nkt - 2);
#pragma unroll
        for (int mi = 0; mi < 2; mi++) {
            int rowm = rbase + mi * 16;
#pragma unroll
            for (int nf = 0; nf < 8; nf++) {
                int kg = k0 + nf * 8 + 2 * jp;
#pragma unroll
                for (int e = 0; e < 4; e++) {
                    int col = kg + (e & 1);
                    int row = rowm + ((e >= 2) ? 8 : 0);
                    float v = facc[mi][nf][e] * scale2;
                    if (diag && col > row) v = -1e30f;
                    facc[mi][nf][e] = v;
                }
            }
            float mx0 = -1e30f, mx1 = -1e30f;
#pragma unroll
            for (int nf = 0; nf < 8; nf++) {
                mx0 = fmaxf(mx0, fmaxf(facc[mi][nf][0], facc[mi][nf][1]));
                mx1 = fmaxf(mx1, fmaxf(facc[mi][nf][2], facc[mi][nf][3]));
            }
            mx0 = fmaxf(mx0, __shfl_xor_sync(0xffffffffu, mx0, 1));
            mx0 = fmaxf(mx0, __shfl_xor_sync(0xffffffffu, mx0, 2));
            mx1 = fmaxf(mx1, __shfl_xor_sync(0xffffffffu, mx1, 1));
            mx1 = fmaxf(mx1, __shfl_xor_sync(0xffffffffu, mx1, 2));
            float nm0 = fmaxf(mm[mi][0], mx0), nm1 = fmaxf(mm[mi][1], mx1);
            float al0 = ex2(mm[mi][0] - nm0), al1 = ex2(mm[mi][1] - nm1);
            mm[mi][0] = nm0; mm[mi][1] = nm1;
            float rs0 = 0.f, rs1 = 0.f;
#pragma unroll
            for (int nf = 0; nf < 8; nf++) {
                facc[mi][nf][0] = ex2(facc[mi][nf][0] - nm0);
                facc[mi][nf][1] = ex2(facc[mi][nf][1] - nm0);
                facc[mi][nf][2] = ex2(facc[mi][nf][2] - nm1);
                facc[mi][nf][3] = ex2(facc[mi][nf][3] - nm1);
                rs0 += facc[mi][nf][0] + facc[mi][nf][1];
                rs1 += facc[mi][nf][2] + facc[mi][nf][3];
            }
            rs0 += __shfl_xor_sync(0xffffffffu, rs0, 1);
            rs0 += __shfl_xor_sync(0xffffffffu, rs0, 2);
            rs1 += __shfl_xor_sync(0xffffffffu, rs1, 1);
            rs1 += __shfl_xor_sync(0xffffffffu, rs1, 2);
            ll[mi][0] = ll[mi][0] * al0 + rs0;
            ll[mi][1] = ll[mi][1] * al1 + rs1;
#pragma unroll
            for (int dn = 0; dn < 8; dn++) {
                oacc[mi][dn][0] *= al0; oacc[mi][dn][1] *= al0;
                oacc[mi][dn][2] *= al1; oacc[mi][dn][3] *= al1;
            }
        }

        // ---- O += P @ V : transpose P acc->A-frag via shfl; share V frags ----
        int srcA = (lane & 28) | (jp >> 1);
        bool odd = jp & 1;
#pragma unroll
        for (int kt8 = 0; kt8 < 8; kt8++) {
            uint32_t pa[2][4];
#pragma unroll
            for (int mi = 0; mi < 2; mi++) {
                uint32_t pc0 = f2tf32(facc[mi][kt8][0]);
                uint32_t pc1 = f2tf32(facc[mi][kt8][1]);
                uint32_t pc2 = f2tf32(facc[mi][kt8][2]);
                uint32_t pc3 = f2tf32(facc[mi][kt8][3]);
                uint32_t s0 = __shfl_sync(0xffffffffu, pc0, srcA);
                uint32_t s1 = __shfl_sync(0xffffffffu, pc1, srcA);
                uint32_t s2 = __shfl_sync(0xffffffffu, pc2, srcA);
                uint32_t s3 = __shfl_sync(0xffffffffu, pc3, srcA);
                uint32_t u0 = __shfl_sync(0xffffffffu, pc0, srcA + 2);
                uint32_t u1 = __shfl_sync(0xffffffffu, pc1, srcA + 2);
                uint32_t u2 = __shfl_sync(0xffffffffu, pc2, srcA + 2);
                uint32_t u3 = __shfl_sync(0xffffffffu, pc3, srcA + 2);
                pa[mi][0] = odd ? s1 : s0;
                pa[mi][1] = odd ? s3 : s2;
                pa[mi][2] = odd ? u1 : u0;
                pa[mi][3] = odd ? u3 : u2;
            }
#pragma unroll
            for (int dn = 0; dn < 8; dn++) {
                uint32_t bfr[2];
                bfr[0] = __float_as_uint(Vs[(kt8 * 8 + jp) * VSTR + dn * 8 + qq]);
                bfr[1] = __float_as_uint(Vs[(kt8 * 8 + jp + 4) * VSTR + dn * 8 + qq]);
                mma_tf32(oacc[0][dn], pa[0], bfr);
                mma_tf32(oacc[1][dn], pa[1], bfr);
            }
        }

        __syncthreads();
        if (t + 2 < nkt) {
            load_kv(t + 2, buf);
            CP_WAIT(1);
        } else {
            CP_WAIT(0);
        }
        __syncthreads();
    }

    // ---- epilogue: normalize, round to tf32, write z ----
#pragma unroll
    for (int mi = 0; mi < 2; mi++) {
        float inv0 = 1.f / ll[mi][0], inv1 = 1.f / ll[mi][1];
        int rowm = rbase + mi * 16;
        float* zp0 = g_z + (size_t)(b * SEQ + rowm) * DM + head * HD;
        float* zp8 = zp0 + (size_t)8 * DM;
#pragma unroll
        for (int dn = 0; dn < 8; dn++) {
            int col = dn * 8 + 2 * jp;
            float2 o0, o1;
            o0.x = rnd(oacc[mi][dn][0] * inv0);
            o0.y = rnd(oacc[mi][dn][1] * inv0);
            o1.x = rnd(oacc[mi][dn][2] * inv1);
            o1.y = rnd(oacc[mi][dn][3] * inv1);
            *(float2*)(zp0 + col) = o0;
            *(float2*)(zp8 + col) = o1;
        }
    }
}

// ---------------------------------------------------------------------------
extern "C" void kernel_launch(void* const* d_in, const int* in_sizes, int n_in,
                              void* d_out, int out_size) {
    const float* x  = (const float*)d_in[0];
    const float* WQ = (const float*)d_in[1];
    const float* WK = (const float*)d_in[2];
    const float* WV = (const float*)d_in[3];
    const float* WO = (const float*)d_in[4];
    const float* bQ = (const float*)d_in[5];
    const float* bK = (const float*)d_in[6];
    const float* bV = (const float*)d_in[7];
    const float* bO = (const float*)d_in[8];
    float* out = (float*)d_out;

    float *xr, *wqkvT, *woT, *bqkv, *qkv, *z;
    cudaGetSymbolAddress((void**)&xr,    g_xr);
    cudaGetSymbolAddress((void**)&wqkvT, g_wqkvT);
    cudaGetSymbolAddress((void**)&woT,   g_woT);
    cudaGetSymbolAddress((void**)&bqkv,  g_bqkv);
    cudaGetSymbolAddress((void**)&qkv,   g_qkv);
    cudaGetSymbolAddress((void**)&z,     g_z);

    cudaFuncSetAttribute(gemm_mma_kernel<true>,
                         cudaFuncAttributeMaxDynamicSharedMemorySize, GEMM_SMEM);
    cudaFuncSetAttribute(gemm_mma_kernel<false>,
                         cudaFuncAttributeMaxDynamicSharedMemorySize, GEMM_SMEM);
    cudaFuncSetAttribute(attn_mma_kernel,
                         cudaFuncAttributeMaxDynamicSharedMemorySize, ATT_SMEM);

    // 1) round x + pack weights (transposed, k-interleaved, tf32) + bias
    round_x_kernel<<<(TOK * DM / 4) / 256, 256>>>(x);
    pack_w_kernel<<<(QKVC * DM + 255) / 256, 256>>>(WQ, WK, WV, WO, bQ, bK, bV);

    // 2) QKV projection (output rounded -> attention operands)
    {
        dim3 grid(QKVC / BN, TOK / BM);
        gemm_mma_kernel<true><<<grid, 128, GEMM_SMEM>>>(xr, wqkvT, bqkv, qkv, QKVC);
    }

    // 3) causal flash attention -> z (rounded)
    {
        dim3 grid(SEQ / AQ, NHEADS, BATCH);
        attn_mma_kernel<<<grid, 128, ATT_SMEM>>>();
    }

    // 4) output projection (final fp32, no rounding)
    {
        dim3 grid(DM / BN, TOK / BM);
        gemm_mma_kernel<false><<<grid, 128, GEMM_SMEM>>>(z, woT, bO, out, DM);
    }
}